// round 5
// baseline (speedup 1.0000x reference)
#include <cuda_runtime.h>
#include <cuda_fp16.h>
#include <cstdint>

// Problem dims
#define GM 512      // batch
#define GK 4096     // IN
#define GN 11008    // OUT

// Fused GEMM tiling: BM=512 (all batch), BN=64, split-K by 4
#define BN      64
#define BK      64
#define KSPLIT  4
#define KRANGE  (GK / KSPLIT)     // 1024
#define NK      (KRANGE / BK)     // 16 k-tiles per CTA
#define NTILES  (GN / BN)         // 172
#define THREADS 512
#define PAD     8
#define LDS_K   (BK + PAD)        // 72 halves -> 144B row stride, ldmatrix conflict-free

// fp16 x scratch (allocation-free rule: __device__ global)
__device__ __half g_x[(size_t)GM * GK];   // 4MB, L2-resident

// ---------------------------------------------------------------------------
__device__ __forceinline__ uint32_t smem_u32(const void* p) {
    return (uint32_t)__cvta_generic_to_shared(p);
}
__device__ __forceinline__ void cp_async16(void* smem, const void* gmem) {
    asm volatile("cp.async.cg.shared.global [%0], [%1], 16;\n"
                 ::"r"(smem_u32(smem)), "l"(gmem));
}

// ---------------------------------------------------------------------------
// x fp32 -> fp16 pre-convert
// ---------------------------------------------------------------------------
__global__ void k_convert_x(const float* __restrict__ x) {
    const int n4 = GM * GK / 4;
    uint2* xo = (uint2*)g_x;
    const float4* xi = (const float4*)x;
    for (int i = blockIdx.x * blockDim.x + threadIdx.x; i < n4;
         i += gridDim.x * blockDim.x) {
        float4 v = xi[i];
        __half2 a = __floats2half2_rn(v.x, v.y);
        __half2 b = __floats2half2_rn(v.z, v.w);
        uint2 o;
        o.x = *(unsigned int*)&a;
        o.y = *(unsigned int*)&b;
        xo[i] = o;
    }
}

// out[b][o] = bias[o]   (split-K partials are red.add'ed on top)
__global__ void k_init_out(const float* __restrict__ bias, float* __restrict__ out) {
    const int n4 = GM * GN / 4;
    const int gn4 = GN / 4;
    float4* o4 = (float4*)out;
    const float4* b4 = (const float4*)bias;
    for (int i = blockIdx.x * blockDim.x + threadIdx.x; i < n4;
         i += gridDim.x * blockDim.x) {
        o4[i] = b4[i % gn4];
    }
}

// out *= scale[o]
__global__ void k_finalize(const float* __restrict__ scale, float* __restrict__ out) {
    const int n4 = GM * GN / 4;
    const int gn4 = GN / 4;
    float4* o4 = (float4*)out;
    const float4* s4 = (const float4*)scale;
    for (int i = blockIdx.x * blockDim.x + threadIdx.x; i < n4;
         i += gridDim.x * blockDim.x) {
        float4 v = o4[i];
        float4 s = s4[i % gn4];
        v.x *= s.x; v.y *= s.y; v.z *= s.z; v.w *= s.w;
        o4[i] = v;
    }
}

// ---------------------------------------------------------------------------
// Fused: decompress W tile (LDG int32 -> LUT -> smem fp16) + X via cp.async,
// mma.sync m16n8k16 GEMM, split-K partials red.add'ed into out.
// Grid: (NTILES, KSPLIT). 512 threads = 16 warps = 8(m) x 2(n), warp tile 64x32.
// ---------------------------------------------------------------------------
#define SMEM_DYN (2 * (GM * LDS_K + BN * LDS_K) * 2)

__global__ void __launch_bounds__(THREADS, 1)
k_fused(const int* __restrict__ stored, const int* __restrict__ sign,
        const float* __restrict__ lmin_p, const float* __restrict__ lmax_p,
        float* __restrict__ out) {
    extern __shared__ __half dynsmem[];
    __shared__ unsigned short lut[256];

    // layout: As[2][512][72], Ws[2][64][72]
    __half* As[2] = {dynsmem, dynsmem + GM * LDS_K};
    __half* Wsm[2] = {dynsmem + 2 * GM * LDS_K, dynsmem + 2 * GM * LDS_K + BN * LDS_K};

    const int tid = threadIdx.x;
    const int lane = tid & 31;
    const int warp = tid >> 5;
    const int wm = warp >> 1;   // 0..7 over M
    const int wn = warp & 1;    // 0..1 over N
    const int n0 = blockIdx.x * BN;
    const int kbase = blockIdx.y * KRANGE;

    {
        float lmin = *lmin_p;
        float lrange = *lmax_p - lmin;
        for (int i = tid; i < 256; i += THREADS) {
            float lw = lmin + ((255.0f - (float)i) * (1.0f / 254.0f)) * lrange;
            lut[i] = __half_as_ushort(__float2half_rn(__expf(lw)));
        }
    }
    __syncthreads();

    float acc[4][4][4];
#pragma unroll
    for (int a = 0; a < 4; a++)
#pragma unroll
        for (int b = 0; b < 4; b++)
#pragma unroll
            for (int c = 0; c < 4; c++) acc[a][b][c] = 0.f;

    // W decompress mapping: thread -> (row = tid>>3 in 0..63, chunk c = tid&7)
    const int wrow = tid >> 3;
    const int wc = tid & 7;
    const size_t wgoff = (size_t)(n0 + wrow) * GK + kbase + wc * 8;

    // X cp.async mapping: 4096 16B-chunks per stage, 8 per thread
    auto load_x = [&](int st, int kt) {
        const int kk = kbase + kt * BK;
#pragma unroll
        for (int j = 0; j < 8; ++j) {
            int t = tid + j * THREADS;     // 0..4095
            int row = t >> 3;              // batch 0..511
            int cx = t & 7;                // 16B chunk
            cp_async16(As[st] + row * LDS_K + cx * 8,
                       g_x + (size_t)row * GK + kk + cx * 8);
        }
    };

    // W prefetch regs
    int4 sa, sb, ga, gb;
    auto load_w = [&](int kt) {
        const int4* sp = (const int4*)(stored + wgoff + (size_t)kt * BK);
        const int4* gp = (const int4*)(sign + wgoff + (size_t)kt * BK);
        sa = sp[0]; sb = sp[1];
        ga = gp[0]; gb = gp[1];
    };
    auto store_w = [&](int st) {
        unsigned int h0 = lut[sa.x] ^ ((((unsigned)ga.x) >> 16) & 0x8000u);
        unsigned int h1 = lut[sa.y] ^ ((((unsigned)ga.y) >> 16) & 0x8000u);
        unsigned int h2 = lut[sa.z] ^ ((((unsigned)ga.z) >> 16) & 0x8000u);
        unsigned int h3 = lut[sa.w] ^ ((((unsigned)ga.w) >> 16) & 0x8000u);
        unsigned int h4 = lut[sb.x] ^ ((((unsigned)gb.x) >> 16) & 0x8000u);
        unsigned int h5 = lut[sb.y] ^ ((((unsigned)gb.y) >> 16) & 0x8000u);
        unsigned int h6 = lut[sb.z] ^ ((((unsigned)gb.z) >> 16) & 0x8000u);
        unsigned int h7 = lut[sb.w] ^ ((((unsigned)gb.w) >> 16) & 0x8000u);
        uint4 o;
        o.x = h0 | (h1 << 16);
        o.y = h2 | (h3 << 16);
        o.z = h4 | (h5 << 16);
        o.w = h6 | (h7 << 16);
        *(uint4*)(Wsm[st] + wrow * LDS_K + wc * 8) = o;
    };

    // prologue
    load_w(0);
    load_x(0, 0);
    asm volatile("cp.async.commit_group;\n" ::: "memory");
    load_x(1, 1);
    asm volatile("cp.async.commit_group;\n" ::: "memory");

    const int arow = lane & 15;
    const int acol = (lane >> 4) * 8;

    for (int kt = 0; kt < NK; ++kt) {
        const int s = kt & 1;
        asm volatile("cp.async.wait_group 1;\n" ::: "memory");
        store_w(s);                      // decompress current W regs -> smem
        if (kt + 1 < NK) load_w(kt + 1); // prefetch next W (latency hides behind MMA)
        __syncthreads();                 // stage s complete (X + W)

#pragma unroll
        for (int ks = 0; ks < BK / 16; ++ks) {
            unsigned int afr[4][4];
            unsigned int bfr[4][2];
#pragma unroll
            for (int mi = 0; mi < 4; ++mi) {
                unsigned int addr = smem_u32(
                    As[s] + (wm * 64 + mi * 16 + arow) * LDS_K + ks * 16 + acol);
                asm volatile(
                    "ldmatrix.sync.aligned.m8n8.x4.shared.b16 {%0,%1,%2,%3}, [%4];\n"
                    : "=r"(afr[mi][0]), "=r"(afr[mi][1]), "=r"(afr[mi][2]),
                      "=r"(afr[mi][3])
                    : "r"(addr));
            }
#pragma unroll
            for (int nj = 0; nj < 2; ++nj) {
                unsigned int q0, q1, q2, q3;
                unsigned int addr = smem_u32(
                    Wsm[s] + (wn * 32 + nj * 16 + arow) * LDS_K + ks * 16 + acol);
                asm volatile(
                    "ldmatrix.sync.aligned.m8n8.x4.shared.b16 {%0,%1,%2,%3}, [%4];\n"
                    : "=r"(q0), "=r"(q1), "=r"(q2), "=r"(q3)
                    : "r"(addr));
                bfr[nj * 2][0] = q0;
                bfr[nj * 2][1] = q2;
                bfr[nj * 2 + 1][0] = q1;
                bfr[nj * 2 + 1][1] = q3;
            }
#pragma unroll
            for (int mi = 0; mi < 4; ++mi)
#pragma unroll
                for (int nf = 0; nf < 4; ++nf) {
                    asm volatile(
                        "mma.sync.aligned.m16n8k16.row.col.f32.f16.f16.f32 "
                        "{%0,%1,%2,%3}, {%4,%5,%6,%7}, {%8,%9}, {%0,%1,%2,%3};\n"
                        : "+f"(acc[mi][nf][0]), "+f"(acc[mi][nf][1]),
                          "+f"(acc[mi][nf][2]), "+f"(acc[mi][nf][3])
                        : "r"(afr[mi][0]), "r"(afr[mi][1]), "r"(afr[mi][2]),
                          "r"(afr[mi][3]), "r"(bfr[nf][0]), "r"(bfr[nf][1]));
                }
        }
        __syncthreads();                 // stage-s readers done before reuse at kt+2
        if (kt + 2 < NK) load_x(s, kt + 2);
        asm volatile("cp.async.commit_group;\n" ::: "memory");
    }

    // epilogue: red.add partial into out (out pre-initialized with bias)
    const int row = lane >> 2;
    const int col2 = (lane & 3) * 2;
#pragma unroll
    for (int mi = 0; mi < 4; ++mi) {
        int m0 = wm * 64 + mi * 16 + row;   // global batch (BM == GM)
#pragma unroll
        for (int nf = 0; nf < 4; ++nf) {
            int nn = n0 + wn * 32 + nf * 8 + col2;
            atomicAdd(&out[(size_t)m0 * GN + nn],           acc[mi][nf][0]);
            atomicAdd(&out[(size_t)m0 * GN + nn + 1],       acc[mi][nf][1]);
            atomicAdd(&out[(size_t)(m0 + 8) * GN + nn],     acc[mi][nf][2]);
            atomicAdd(&out[(size_t)(m0 + 8) * GN + nn + 1], acc[mi][nf][3]);
        }
    }
}

// ---------------------------------------------------------------------------
extern "C" void kernel_launch(void* const* d_in, const int* in_sizes, int n_in,
                              void* d_out, int out_size) {
    const float* x      = (const float*)d_in[0];
    const int*   stored = (const int*)d_in[1];
    const int*   sign   = (const int*)d_in[2];
    const float* lmin   = (const float*)d_in[3];
    const float* lmax   = (const float*)d_in[4];
    const float* scale  = (const float*)d_in[5];
    const float* bias   = (const float*)d_in[6];
    float* out = (float*)d_out;

    cudaFuncSetAttribute(k_fused, cudaFuncAttributeMaxDynamicSharedMemorySize, SMEM_DYN);

    k_convert_x<<<512, 256>>>(x);
    k_init_out<<<1024, 256>>>(bias, out);
    dim3 grid(NTILES, KSPLIT);   // (172, 4)
    k_fused<<<grid, THREADS, SMEM_DYN>>>(stored, sign, lmin, lmax, out);
    k_finalize<<<1024, 256>>>(scale, out);
}

// round 6
// speedup vs baseline: 1.0166x; 1.0166x over previous
#include <cuda_runtime.h>
#include <cuda_fp16.h>
#include <cstdint>

// Problem dims
#define GM 512      // batch
#define GK 4096     // IN
#define GN 11008    // OUT

// Fused GEMM tiling: BM=512 (all batch), BN=64, split-K by 4
#define BN      64
#define BK      64
#define KSPLIT  4
#define KRANGE  (GK / KSPLIT)     // 1024
#define NK      (KRANGE / BK)     // 16 k-tiles per CTA
#define NTILES  (GN / BN)         // 172
#define THREADS 512
#define PAD     8
#define LDS_K   (BK + PAD)        // 72 halves -> 144B row stride, ldmatrix conflict-free

// Scratch (allocation-free rule: __device__ globals)
__device__ __half g_x[(size_t)GM * GK];                    // 4MB fp16 x, L2-resident
__device__ float  g_part[(size_t)KSPLIT * GM * GN];        // 90MB split-K partials

// ---------------------------------------------------------------------------
__device__ __forceinline__ uint32_t smem_u32(const void* p) {
    return (uint32_t)__cvta_generic_to_shared(p);
}
__device__ __forceinline__ void cp_async16(void* smem, const void* gmem) {
    asm volatile("cp.async.cg.shared.global [%0], [%1], 16;\n"
                 ::"r"(smem_u32(smem)), "l"(gmem));
}

// ---------------------------------------------------------------------------
// x fp32 -> fp16 pre-convert
// ---------------------------------------------------------------------------
__global__ void k_convert_x(const float* __restrict__ x) {
    const int n4 = GM * GK / 4;
    uint2* xo = (uint2*)g_x;
    const float4* xi = (const float4*)x;
    for (int i = blockIdx.x * blockDim.x + threadIdx.x; i < n4;
         i += gridDim.x * blockDim.x) {
        float4 v = xi[i];
        __half2 a = __floats2half2_rn(v.x, v.y);
        __half2 b = __floats2half2_rn(v.z, v.w);
        uint2 o;
        o.x = *(unsigned int*)&a;
        o.y = *(unsigned int*)&b;
        xo[i] = o;
    }
}

// out = (sum_{s<4} part[s] + bias) * scale, vectorized
__global__ void k_finalize(const float* __restrict__ scale,
                           const float* __restrict__ bias,
                           float* __restrict__ out) {
    const int n4 = GM * GN / 4;
    const int gn4 = GN / 4;
    const size_t stride = (size_t)GM * GN / 4;
    float4* o4 = (float4*)out;
    const float4* p4 = (const float4*)g_part;
    const float4* b4 = (const float4*)bias;
    const float4* s4 = (const float4*)scale;
    for (int i = blockIdx.x * blockDim.x + threadIdx.x; i < n4;
         i += gridDim.x * blockDim.x) {
        float4 a0 = p4[i];
        float4 a1 = p4[i + stride];
        float4 a2 = p4[i + 2 * stride];
        float4 a3 = p4[i + 3 * stride];
        int c = i % gn4;
        float4 b = b4[c];
        float4 s = s4[c];
        float4 r;
        r.x = ((a0.x + a1.x) + (a2.x + a3.x) + b.x) * s.x;
        r.y = ((a0.y + a1.y) + (a2.y + a3.y) + b.y) * s.y;
        r.z = ((a0.z + a1.z) + (a2.z + a3.z) + b.z) * s.z;
        r.w = ((a0.w + a1.w) + (a2.w + a3.w) + b.w) * s.w;
        o4[i] = r;
    }
}

// ---------------------------------------------------------------------------
// Fused: decompress W tile (LDG int32 -> LUT -> smem fp16) + X via cp.async,
// mma.sync m16n8k16 GEMM. Split-K partials -> plain STG into g_part (NO atomics).
// Grid: (NTILES, KSPLIT). 512 threads = 16 warps = 8(m) x 2(n), warp tile 64x32.
// ---------------------------------------------------------------------------
#define SMEM_DYN (2 * (GM * LDS_K + BN * LDS_K) * 2)

__global__ void __launch_bounds__(THREADS, 1)
k_fused(const int* __restrict__ stored, const int* __restrict__ sign,
        const float* __restrict__ lmin_p, const float* __restrict__ lmax_p) {
    extern __shared__ __half dynsmem[];
    __shared__ unsigned short lut[256];

    // layout: As[2][512][72], Ws[2][64][72]
    __half* As[2] = {dynsmem, dynsmem + GM * LDS_K};
    __half* Wsm[2] = {dynsmem + 2 * GM * LDS_K, dynsmem + 2 * GM * LDS_K + BN * LDS_K};

    const int tid = threadIdx.x;
    const int lane = tid & 31;
    const int warp = tid >> 5;
    const int wm = warp >> 1;   // 0..7 over M
    const int wn = warp & 1;    // 0..1 over N
    const int n0 = blockIdx.x * BN;
    const int kbase = blockIdx.y * KRANGE;

    {
        float lmin = *lmin_p;
        float lrange = *lmax_p - lmin;
        for (int i = tid; i < 256; i += THREADS) {
            float lw = lmin + ((255.0f - (float)i) * (1.0f / 254.0f)) * lrange;
            lut[i] = __half_as_ushort(__float2half_rn(__expf(lw)));
        }
    }
    __syncthreads();

    float acc[4][4][4];
#pragma unroll
    for (int a = 0; a < 4; a++)
#pragma unroll
        for (int b = 0; b < 4; b++)
#pragma unroll
            for (int c = 0; c < 4; c++) acc[a][b][c] = 0.f;

    // W decompress mapping: thread -> (row = tid>>3 in 0..63, chunk c = tid&7)
    const int wrow = tid >> 3;
    const int wc = tid & 7;
    const size_t wgoff = (size_t)(n0 + wrow) * GK + kbase + wc * 8;

    // X cp.async mapping: 4096 16B-chunks per stage, 8 per thread
    auto load_x = [&](int st, int kt) {
        const int kk = kbase + kt * BK;
#pragma unroll
        for (int j = 0; j < 8; ++j) {
            int t = tid + j * THREADS;     // 0..4095
            int row = t >> 3;              // batch 0..511
            int cx = t & 7;                // 16B chunk
            cp_async16(As[st] + row * LDS_K + cx * 8,
                       g_x + (size_t)row * GK + kk + cx * 8);
        }
    };

    // W prefetch regs
    int4 sa, sb, ga, gb;
    auto load_w = [&](int kt) {
        const int4* sp = (const int4*)(stored + wgoff + (size_t)kt * BK);
        const int4* gp = (const int4*)(sign + wgoff + (size_t)kt * BK);
        sa = sp[0]; sb = sp[1];
        ga = gp[0]; gb = gp[1];
    };
    auto store_w = [&](int st) {
        unsigned int h0 = lut[sa.x] ^ ((((unsigned)ga.x) >> 16) & 0x8000u);
        unsigned int h1 = lut[sa.y] ^ ((((unsigned)ga.y) >> 16) & 0x8000u);
        unsigned int h2 = lut[sa.z] ^ ((((unsigned)ga.z) >> 16) & 0x8000u);
        unsigned int h3 = lut[sa.w] ^ ((((unsigned)ga.w) >> 16) & 0x8000u);
        unsigned int h4 = lut[sb.x] ^ ((((unsigned)gb.x) >> 16) & 0x8000u);
        unsigned int h5 = lut[sb.y] ^ ((((unsigned)gb.y) >> 16) & 0x8000u);
        unsigned int h6 = lut[sb.z] ^ ((((unsigned)gb.z) >> 16) & 0x8000u);
        unsigned int h7 = lut[sb.w] ^ ((((unsigned)gb.w) >> 16) & 0x8000u);
        uint4 o;
        o.x = h0 | (h1 << 16);
        o.y = h2 | (h3 << 16);
        o.z = h4 | (h5 << 16);
        o.w = h6 | (h7 << 16);
        *(uint4*)(Wsm[st] + wrow * LDS_K + wc * 8) = o;
    };

    // prologue
    load_w(0);
    load_x(0, 0);
    asm volatile("cp.async.commit_group;\n" ::: "memory");
    load_x(1, 1);
    asm volatile("cp.async.commit_group;\n" ::: "memory");

    const int arow = lane & 15;
    const int acol = (lane >> 4) * 8;

    for (int kt = 0; kt < NK; ++kt) {
        const int s = kt & 1;
        asm volatile("cp.async.wait_group 1;\n" ::: "memory");
        store_w(s);                      // decompress current W regs -> smem
        if (kt + 1 < NK) load_w(kt + 1); // prefetch next W (latency hides behind MMA)
        __syncthreads();                 // stage s complete (X + W)

#pragma unroll
        for (int ks = 0; ks < BK / 16; ++ks) {
            unsigned int afr[4][4];
            unsigned int bfr[4][2];
#pragma unroll
            for (int mi = 0; mi < 4; ++mi) {
                unsigned int addr = smem_u32(
                    As[s] + (wm * 64 + mi * 16 + arow) * LDS_K + ks * 16 + acol);
                asm volatile(
                    "ldmatrix.sync.aligned.m8n8.x4.shared.b16 {%0,%1,%2,%3}, [%4];\n"
                    : "=r"(afr[mi][0]), "=r"(afr[mi][1]), "=r"(afr[mi][2]),
                      "=r"(afr[mi][3])
                    : "r"(addr));
            }
#pragma unroll
            for (int nj = 0; nj < 2; ++nj) {
                unsigned int q0, q1, q2, q3;
                unsigned int addr = smem_u32(
                    Wsm[s] + (wn * 32 + nj * 16 + arow) * LDS_K + ks * 16 + acol);
                asm volatile(
                    "ldmatrix.sync.aligned.m8n8.x4.shared.b16 {%0,%1,%2,%3}, [%4];\n"
                    : "=r"(q0), "=r"(q1), "=r"(q2), "=r"(q3)
                    : "r"(addr));
                bfr[nj * 2][0] = q0;
                bfr[nj * 2][1] = q2;
                bfr[nj * 2 + 1][0] = q1;
                bfr[nj * 2 + 1][1] = q3;
            }
#pragma unroll
            for (int mi = 0; mi < 4; ++mi)
#pragma unroll
                for (int nf = 0; nf < 4; ++nf) {
                    asm volatile(
                        "mma.sync.aligned.m16n8k16.row.col.f32.f16.f16.f32 "
                        "{%0,%1,%2,%3}, {%4,%5,%6,%7}, {%8,%9}, {%0,%1,%2,%3};\n"
                        : "+f"(acc[mi][nf][0]), "+f"(acc[mi][nf][1]),
                          "+f"(acc[mi][nf][2]), "+f"(acc[mi][nf][3])
                        : "r"(afr[mi][0]), "r"(afr[mi][1]), "r"(afr[mi][2]),
                          "r"(afr[mi][3]), "r"(bfr[nf][0]), "r"(bfr[nf][1]));
                }
        }
        __syncthreads();                 // stage-s readers done before reuse at kt+2
        if (kt + 2 < NK) load_x(s, kt + 2);
        asm volatile("cp.async.commit_group;\n" ::: "memory");
    }

    // epilogue: plain STG of this split's partial tile (no atomics)
    float* po = g_part + (size_t)blockIdx.y * GM * GN;
    const int row = lane >> 2;
    const int col2 = (lane & 3) * 2;
#pragma unroll
    for (int mi = 0; mi < 4; ++mi) {
        int m0 = wm * 64 + mi * 16 + row;   // global batch (BM == GM)
#pragma unroll
        for (int nf = 0; nf < 4; ++nf) {
            int nn = n0 + wn * 32 + nf * 8 + col2;
            float2 v0 = make_float2(acc[mi][nf][0], acc[mi][nf][1]);
            float2 v1 = make_float2(acc[mi][nf][2], acc[mi][nf][3]);
            *(float2*)&po[(size_t)m0 * GN + nn] = v0;
            *(float2*)&po[(size_t)(m0 + 8) * GN + nn] = v1;
        }
    }
}

// ---------------------------------------------------------------------------
extern "C" void kernel_launch(void* const* d_in, const int* in_sizes, int n_in,
                              void* d_out, int out_size) {
    const float* x      = (const float*)d_in[0];
    const int*   stored = (const int*)d_in[1];
    const int*   sign   = (const int*)d_in[2];
    const float* lmin   = (const float*)d_in[3];
    const float* lmax   = (const float*)d_in[4];
    const float* scale  = (const float*)d_in[5];
    const float* bias   = (const float*)d_in[6];
    float* out = (float*)d_out;

    cudaFuncSetAttribute(k_fused, cudaFuncAttributeMaxDynamicSharedMemorySize, SMEM_DYN);

    k_convert_x<<<512, 256>>>(x);
    dim3 grid(NTILES, KSPLIT);   // (172, 4)
    k_fused<<<grid, THREADS, SMEM_DYN>>>(stored, sign, lmin, lmax);
    k_finalize<<<2048, 256>>>(scale, bias, out);
}